// round 11
// baseline (speedup 1.0000x reference)
#include <cuda_runtime.h>
#include <math.h>

#define B_ 16
#define C_ 64
#define T_ 2048
#define H_ 4
#define HD_ 16
#define NR_ 1024
#define TOPK_ 40
#define C2_ 128

// ---------------- packed fp32x2 helpers (sm_103a FFMA2) ----------------
__device__ __forceinline__ double pk2(float lo, float hi) {
    double r; asm("mov.b64 %0, {%1,%2};" : "=d"(r) : "f"(lo), "f"(hi)); return r;
}
__device__ __forceinline__ void upk2(double v, float& lo, float& hi) {
    asm("mov.b64 {%0,%1}, %2;" : "=f"(lo), "=f"(hi) : "d"(v));
}
__device__ __forceinline__ void ffma2(double& acc, double a, double b) {
    asm("fma.rn.f32x2 %0, %1, %2, %0;" : "+d"(acc) : "d"(a), "d"(b));
}

// ---------------- scratch (device globals; no allocation) ----------------
__device__ float g_fwq[3*C_*C_];
__device__ float g_fwk[3*C_*C_];
__device__ float g_fwv[C_*C_];
__device__ float g_bq3[3*C_];
__device__ float g_bk3[3*C_];
__device__ float g_bv [C_];
__device__ float g_v  [B_*C_*T_];
__device__ float g_qr [B_*C_*NR_];
__device__ float g_kr [B_*C_*NR_];
__device__ float g_ar [B_*NR_*NR_];
__device__ int   g_idx[B_*NR_*TOPK_];
__device__ float g_qbt[B_*NR_*128];
__device__ float g_kbt[B_*NR_*128];
__device__ float g_vbt[B_*NR_*128];
__device__ float g_obt[B_*NR_*128];
__device__ float g_x2 [B_*C_*T_];
__device__ float g_h1 [B_*C2_*T_];
__device__ float g_h2 [B_*C2_*T_];
__device__ float2 g_tw[1024];

__device__ __forceinline__ float bnsc(float g) { return g * rsqrtf(1.0f + 1e-5f); }

// ---------------- K0: twiddle ----------------
__global__ void twiddle_kernel() {
    int k = blockIdx.x * blockDim.x + threadIdx.x;
    if (k < 1024) {
        double a = -2.0 * 3.14159265358979323846 * (double)k / 2048.0;
        g_tw[k] = make_float2((float)cos(a), (float)sin(a));
    }
}

// ---------------- K1: fold BN into conv weights ----------------
__global__ void __launch_bounds__(256) prep_kernel(const float* __restrict__ n1_g,
                                                   const float* __restrict__ n1_b,
                                                   const float* __restrict__ wq,
                                                   const float* __restrict__ bnq_g,
                                                   const float* __restrict__ bnq_b,
                                                   const float* __restrict__ wk,
                                                   const float* __restrict__ bnk_g,
                                                   const float* __restrict__ bnk_b,
                                                   const float* __restrict__ wv) {
    int tid = threadIdx.x;
    for (int i = tid; i < 3 * C_ * C_; i += 256) {
        int oc = i & 63;
        int ci = (i >> 6) & 63;
        int h  = i >> 12;
        float s1 = bnsc(n1_g[ci]);
        g_fwq[i] = wq[(oc * 64 + ci) * 3 + h] * s1 * bnsc(bnq_g[oc]);
        g_fwk[i] = wk[(oc * 64 + ci) * 3 + h] * s1 * bnsc(bnk_g[oc]);
    }
    for (int i = tid; i < C_ * C_; i += 256) {
        int oc = i & 63, ci = i >> 6;
        g_fwv[i] = wv[oc * 64 + ci] * bnsc(n1_g[ci]);
    }
    if (tid < 64) {
        int oc = tid;
        float Sq[3] = {0.f, 0.f, 0.f}, Sk[3] = {0.f, 0.f, 0.f}, Sv = 0.f;
        for (int ci = 0; ci < 64; ci++) {
            float b1 = n1_b[ci];
#pragma unroll
            for (int h = 0; h < 3; h++) {
                Sq[h] += wq[(oc * 64 + ci) * 3 + h] * b1;
                Sk[h] += wk[(oc * 64 + ci) * 3 + h] * b1;
            }
            Sv += wv[oc * 64 + ci] * b1;
        }
        float sq = bnsc(bnq_g[oc]), sk = bnsc(bnk_g[oc]);
        float mq = sq * (Sq[0] + Sq[1] + Sq[2]) + bnq_b[oc];
        float mk = sk * (Sk[0] + Sk[1] + Sk[2]) + bnk_b[oc];
        g_bq3[oc]       = mq - sq * Sq[0];
        g_bq3[64 + oc]  = mq;
        g_bq3[128 + oc] = mq - sq * Sq[2];
        g_bk3[oc]       = mk - sk * Sk[0];
        g_bk3[64 + oc]  = mk;
        g_bk3[128 + oc] = mk - sk * Sk[2];
        g_bv[oc] = Sv;
    }
}

// ---------------- K2: conv k=3 + BN folded (FFMA2), round-9 body + blk0 ----------------
__global__ void __launch_bounds__(128) conv3qk_kernel(const float* __restrict__ x, int blk0) {
    int blk = blk0 + blockIdx.x;
    int oh = blk & 1;
    int tt0 = ((blk >> 1) & 15) * 128;
    int b  = (blk >> 5) & 15;
    int which = blk >> 9;

    const float* w   = which ? g_fwk : g_fwq;
    const float* b3  = which ? g_bk3 : g_bq3;
    float* bt        = which ? g_kbt : g_qbt;
    float* pr        = which ? g_kr  : g_qr;

    __shared__ float s_in[32 * 132];
    __shared__ float s_w[3 * 32 * 32];

    int tid = threadIdx.x;
    int tl4 = (tid & 31) * 4;
    int og  = tid >> 5;

    double acc2[4][4];
#pragma unroll
    for (int t = 0; t < 4; t++)
#pragma unroll
        for (int j = 0; j < 4; j++) acc2[t][j] = 0.0;

    for (int chunk = 0; chunk < 2; chunk++) {
        int ci0 = chunk * 32;
        for (int i = tid; i < 32 * 132; i += 128) {
            int ci = i / 132, jj = i % 132;
            int gt = tt0 + jj - 1;
            s_in[i] = (gt >= 0 && gt < T_ && jj < 130) ? x[(b * C_ + ci0 + ci) * T_ + gt] : 0.f;
        }
        for (int i = tid; i < 3072; i += 128) {
            int ocl = i & 31;
            int cil = (i >> 5) & 31;
            int h = i >> 10;
            s_w[i] = w[(h * 64 + ci0 + cil) * 64 + oh * 32 + ocl];
        }
        __syncthreads();
        for (int cil = 0; cil < 32; cil++) {
            float xs[6];
            float4 xa = *(const float4*)&s_in[cil * 132 + tl4];
            xs[0] = xa.x; xs[1] = xa.y; xs[2] = xa.z; xs[3] = xa.w;
            xs[4] = s_in[cil * 132 + tl4 + 4];
            xs[5] = s_in[cil * 132 + tl4 + 5];
            double px[6];
#pragma unroll
            for (int i = 0; i < 6; i++) px[i] = pk2(xs[i], xs[i]);
#pragma unroll
            for (int h = 0; h < 3; h++) {
                const double* wp = (const double*)&s_w[(h * 32 + cil) * 32 + og * 8];
                double w01 = wp[0], w23 = wp[1], w45 = wp[2], w67 = wp[3];
#pragma unroll
                for (int t = 0; t < 4; t++) {
                    ffma2(acc2[t][0], px[t + h], w01);
                    ffma2(acc2[t][1], px[t + h], w23);
                    ffma2(acc2[t][2], px[t + h], w45);
                    ffma2(acc2[t][3], px[t + h], w67);
                }
            }
        }
        __syncthreads();
    }
    float f[4][8];
#pragma unroll
    for (int t = 0; t < 4; t++)
#pragma unroll
        for (int j = 0; j < 4; j++) upk2(acc2[t][j], f[t][2 * j], f[t][2 * j + 1]);
#pragma unroll
    for (int j = 0; j < 8; j++) {
        int oc = oh * 32 + og * 8 + j;
        float bm = b3[64 + oc];
#pragma unroll
        for (int t = 0; t < 4; t++) {
            int gt = tt0 + tl4 + t;
            float bias = (gt == 0) ? b3[oc] : ((gt == T_ - 1) ? b3[128 + oc] : bm);
            f[t][j] += bias;
        }
        int r0 = (tt0 + tl4) >> 1;
        float2 p2 = make_float2(0.5f * (f[0][j] + f[1][j]), 0.5f * (f[2][j] + f[3][j]));
        *(float2*)&pr[(b * C_ + oc) * NR_ + r0] = p2;
    }
    {
        int h = oh * 2 + (og >> 1);
        int d0 = (og & 1) * 8;
#pragma unroll
        for (int t = 0; t < 4; t++) {
            int gt = tt0 + tl4 + t;
            int r = gt >> 1, s = gt & 1;
            float* dst = &bt[((size_t)(b * NR_ + r) * 4 + h) * 32 + s * 16 + d0];
            *(float4*)dst       = make_float4(f[t][0], f[t][1], f[t][2], f[t][3]);
            *(float4*)(dst + 4) = make_float4(f[t][4], f[t][5], f[t][6], f[t][7]);
        }
    }
}

// ---------------- K3: conv k=1 (v) (FFMA2) ----------------
__global__ void __launch_bounds__(256) conv1v_kernel(const float* __restrict__ x) {
    int blk = blockIdx.x;
    int b = blk >> 5;
    int tt0 = (blk & 31) * 64;
    __shared__ float s_in[64 * 68];
    __shared__ float s_w[64 * 64];
    int tid = threadIdx.x;
    int tq = tid & 15;
    int ocg = tid >> 4;

    for (int i = tid; i < 4096; i += 256) {
        int ci = i >> 6, tl = i & 63;
        s_in[ci * 68 + tl] = x[(b * C_ + ci) * T_ + tt0 + tl];
    }
    for (int i = tid; i < 4096; i += 256) {
        int ci = i >> 6, oc = i & 63;
        s_w[ci * 64 + oc] = g_fwv[ci * 64 + oc];
    }
    __syncthreads();

    double acc2[4][2];
#pragma unroll
    for (int t = 0; t < 4; t++) { acc2[t][0] = 0.0; acc2[t][1] = 0.0; }
    for (int ci = 0; ci < 64; ci++) {
        float4 xa = *(const float4*)&s_in[ci * 68 + tq * 4];
        const double* wp = (const double*)&s_w[ci * 64 + ocg * 4];
        double w01 = wp[0], w23 = wp[1];
        double px[4] = {pk2(xa.x, xa.x), pk2(xa.y, xa.y), pk2(xa.z, xa.z), pk2(xa.w, xa.w)};
#pragma unroll
        for (int t = 0; t < 4; t++) {
            ffma2(acc2[t][0], px[t], w01);
            ffma2(acc2[t][1], px[t], w23);
        }
    }
    float f[4][4];
#pragma unroll
    for (int t = 0; t < 4; t++) {
        upk2(acc2[t][0], f[t][0], f[t][1]);
        upk2(acc2[t][1], f[t][2], f[t][3]);
    }
    int oc0 = ocg * 4;
    {
        float4 bv4 = *(const float4*)&g_bv[oc0];
        float bvr[4] = {bv4.x, bv4.y, bv4.z, bv4.w};
#pragma unroll
        for (int j = 0; j < 4; j++)
#pragma unroll
            for (int t = 0; t < 4; t++) f[t][j] += bvr[j];
    }
#pragma unroll
    for (int j = 0; j < 4; j++) {
        int oc = oc0 + j;
        *(float4*)&g_v[(b * C_ + oc) * T_ + tt0 + tq * 4] =
            make_float4(f[0][j], f[1][j], f[2][j], f[3][j]);
    }
    {
        int h = ocg >> 2;
        int d0 = (ocg & 3) * 4;
#pragma unroll
        for (int t = 0; t < 4; t++) {
            int gt = tt0 + tq * 4 + t;
            int r = gt >> 1, s = gt & 1;
            *(float4*)&g_vbt[((size_t)(b * NR_ + r) * 4 + h) * 32 + s * 16 + d0] =
                make_float4(f[t][0], f[t][1], f[t][2], f[t][3]);
        }
    }
}

// ---------------- K5: a_r (TF32 3x), per-batch half ----------------
__device__ __forceinline__ unsigned f2tf32(float x) {
    unsigned r;
    asm("cvt.rna.tf32.f32 %0, %1;" : "=r"(r) : "f"(x));
    return r;
}
__device__ __forceinline__ void mma_tf32(float* d, unsigned a0, unsigned a1, unsigned a2, unsigned a3,
                                         unsigned b0, unsigned b1) {
    asm("mma.sync.aligned.m16n8k8.row.col.f32.tf32.tf32.f32 "
        "{%0,%1,%2,%3}, {%4,%5,%6,%7}, {%8,%9}, {%0,%1,%2,%3};"
        : "+f"(d[0]), "+f"(d[1]), "+f"(d[2]), "+f"(d[3])
        : "r"(a0), "r"(a1), "r"(a2), "r"(a3), "r"(b0), "r"(b1));
}

__global__ void __launch_bounds__(256) gemm_ar_kernel(int b0) {
    int blk = blockIdx.x;
    int b = b0 + (blk >> 6);
    int mt = (blk >> 3) & 7;
    int nt = blk & 7;
    int m0 = mt * 128, n0 = nt * 128;
    __shared__ float As[128 * 33];
    __shared__ float Bs[128 * 33];
    const float* qp = g_qr + b * C_ * NR_;
    const float* kp = g_kr + b * C_ * NR_;
    int tid = threadIdx.x;
    int warp = tid >> 5, lane = tid & 31;
    int wm = warp >> 2, wn = warp & 3;
    int m0w = wm * 64, n0w = wn * 32;
    int qr = lane >> 2, qc = lane & 3;

    float d[4][4][4];
#pragma unroll
    for (int i = 0; i < 4; i++)
#pragma unroll
        for (int j = 0; j < 4; j++)
#pragma unroll
            for (int q = 0; q < 4; q++) d[i][j][q] = 0.f;

    for (int k0 = 0; k0 < 64; k0 += 32) {
        for (int i = tid; i < 4096; i += 256) {
            int c = i >> 7, m = i & 127;
            As[m * 33 + c] = qp[(k0 + c) * NR_ + m0 + m];
            Bs[m * 33 + c] = kp[(k0 + c) * NR_ + n0 + m];
        }
        __syncthreads();
#pragma unroll
        for (int ks = 0; ks < 32; ks += 8) {
            unsigned ahi[4][4], alo[4][4];
#pragma unroll
            for (int mf = 0; mf < 4; mf++) {
                int rb = (m0w + mf * 16 + qr) * 33 + ks + qc;
                float a[4] = {As[rb], As[rb + 8 * 33], As[rb + 4], As[rb + 8 * 33 + 4]};
#pragma unroll
                for (int q = 0; q < 4; q++) {
                    unsigned h = f2tf32(a[q]);
                    ahi[mf][q] = h;
                    alo[mf][q] = f2tf32(a[q] - __uint_as_float(h));
                }
            }
            unsigned bhi[4][2], blo[4][2];
#pragma unroll
            for (int nf = 0; nf < 4; nf++) {
                int cb = (n0w + nf * 8 + qr) * 33 + ks + qc;
                float bv[2] = {Bs[cb], Bs[cb + 4]};
#pragma unroll
                for (int q = 0; q < 2; q++) {
                    unsigned h = f2tf32(bv[q]);
                    bhi[nf][q] = h;
                    blo[nf][q] = f2tf32(bv[q] - __uint_as_float(h));
                }
            }
#pragma unroll
            for (int mf = 0; mf < 4; mf++)
#pragma unroll
                for (int nf = 0; nf < 4; nf++) {
                    mma_tf32(d[mf][nf], alo[mf][0], alo[mf][1], alo[mf][2], alo[mf][3],
                             bhi[nf][0], bhi[nf][1]);
                    mma_tf32(d[mf][nf], ahi[mf][0], ahi[mf][1], ahi[mf][2], ahi[mf][3],
                             blo[nf][0], blo[nf][1]);
                    mma_tf32(d[mf][nf], ahi[mf][0], ahi[mf][1], ahi[mf][2], ahi[mf][3],
                             bhi[nf][0], bhi[nf][1]);
                }
        }
        __syncthreads();
    }
#pragma unroll
    for (int mf = 0; mf < 4; mf++) {
        int mrow = m0 + m0w + mf * 16 + qr;
#pragma unroll
        for (int nf = 0; nf < 4; nf++) {
            int ncol = n0 + n0w + nf * 8 + 2 * qc;
            *(float2*)&g_ar[(size_t)(b * NR_ + mrow) * NR_ + ncol] =
                make_float2(d[mf][nf][0], d[mf][nf][1]);
            *(float2*)&g_ar[(size_t)(b * NR_ + mrow + 8) * NR_ + ncol] =
                make_float2(d[mf][nf][2], d[mf][nf][3]);
        }
    }
}

// ---------------- K6: top-40, per-batch half ----------------
__global__ void __launch_bounds__(256) topk_kernel(int b0) {
    int row = b0 * NR_ + blockIdx.x;
    int tid = threadIdx.x;
    int lane = tid & 31, wid = tid >> 5;
    unsigned lmlt = (1u << lane) - 1u;
    const float4* ap = (const float4*)(g_ar + (size_t)row * NR_);
    __shared__ int whist[8][256];
    __shared__ int htot[256];
    __shared__ unsigned long long cA[1024];
    __shared__ unsigned long long cB[1024];
    __shared__ int s_thr, s_need, s_outc, s_nsrc, s_nb;

    unsigned long long kv[4];
    {
        float4 v4 = ap[tid];
        float vv[4] = {v4.x, v4.y, v4.z, v4.w};
#pragma unroll
        for (int j = 0; j < 4; j++) {
            unsigned u = __float_as_uint(vv[j]);
            u = (u & 0x80000000u) ? ~u : (u | 0x80000000u);
            kv[j] = ((unsigned long long)u << 32) | (unsigned)(tid * 4 + j);
        }
    }
    if (tid == 0) { s_outc = 0; s_need = TOPK_; }
    int* outp = g_idx + row * TOPK_;

    for (int level = 0; level < 4; level++) {
        unsigned long long* src = (level & 1) ? cA : cB;
        unsigned long long* dst = (level & 1) ? cB : cA;
        int shift = 56 - level * 8;
        if (level == 0) {
            for (int i = tid; i < 2048; i += 256) ((int*)whist)[i] = 0;
            if (tid == 0) s_nb = 0;
            __syncthreads();
#pragma unroll
            for (int j = 0; j < 4; j++)
                atomicAdd(&whist[wid][(int)((kv[j] >> shift) & 255)], 1);
            __syncthreads();
            int sum = 0;
#pragma unroll
            for (int w = 0; w < 8; w++) sum += whist[w][tid];
            htot[tid] = sum;
        } else {
            htot[tid] = 0;
            if (tid == 0) s_nb = 0;
            __syncthreads();
            int nsrc = s_nsrc;
            for (int i = tid; i < nsrc; i += 256)
                atomicAdd(&htot[(int)((src[i] >> shift) & 255)], 1);
        }
        __syncthreads();
        if (tid < 32) {
            int base = 255 - lane * 8;
            int part[8]; int tot = 0;
#pragma unroll
            for (int q = 0; q < 8; q++) { part[q] = htot[base - q]; tot += part[q]; }
            int pre = tot;
#pragma unroll
            for (int o = 1; o < 32; o <<= 1) {
                int v = __shfl_up_sync(0xffffffffu, pre, o);
                if (lane >= o) pre += v;
            }
            pre -= tot;
            int need = s_need;
            int cum = pre;
#pragma unroll
            for (int q = 0; q < 8; q++) {
                int c = part[q];
                if (cum < need && cum + c >= need) s_thr = base - q;
                cum += c;
            }
        }
        __syncthreads();
        int thr = s_thr;
        int nsrc = (level == 0) ? 1024 : s_nsrc;
        int niter = (level == 0) ? 4 : ((nsrc + 255) >> 8);
        for (int it = 0; it < niter; it++) {
            unsigned long long v = 0ull;
            bool valid;
            if (level == 0) { v = kv[it]; valid = true; }
            else { int i = it * 256 + tid; valid = (i < nsrc); if (valid) v = src[i]; }
            int by = valid ? (int)((v >> shift) & 255) : -1;
            bool gt = (by > thr), eq = (by == thr);
            unsigned mg = __ballot_sync(0xffffffffu, gt);
            if (mg) {
                int ldr = __ffs(mg) - 1;
                int bp = 0;
                if (lane == ldr) bp = atomicAdd(&s_outc, __popc(mg));
                bp = __shfl_sync(0xffffffffu, bp, ldr);
                if (gt) outp[bp + __popc(mg & lmlt)] = (int)(v & 0xffffffffu);
            }
            unsigned me = __ballot_sync(0xffffffffu, eq);
            if (me) {
                int ldr = __ffs(me) - 1;
                int bp = 0;
                if (lane == ldr) bp = atomicAdd(&s_nb, __popc(me));
                bp = __shfl_sync(0xffffffffu, bp, ldr);
                if (eq) dst[bp + __popc(me & lmlt)] = v;
            }
        }
        __syncthreads();
        if (tid == 0) { s_need = TOPK_ - s_outc; s_nsrc = s_nb; }
        __syncthreads();
        if (s_nsrc == s_need || level == 3) {
            int base = TOPK_ - s_need;
            for (int i = tid; i < s_need; i += 256)
                outp[base + i] = (int)(dst[i] & 0xffffffffu);
            break;
        }
    }
}

// ---------------- K8: attention (round-9 body: staged K and V) ----------------
__global__ void __launch_bounds__(128) attn_kernel() {
    int blk = blockIdx.x;
    int b = blk >> 10, r = blk & (NR_ - 1);
    int tid = threadIdx.x;
    int lane = tid & 31, h = tid >> 5;
    __shared__ float s_k[40 * 140];
    __shared__ float s_v[40 * 132];
    __shared__ float s_l[4 * 160];
    __shared__ int s_idx[40];

    if (tid < 40) s_idx[tid] = g_idx[(b * NR_ + r) * TOPK_ + tid];
    float qv = g_qbt[((size_t)(b * NR_ + r) * 4 + h) * 32 + lane];
    float q0[16], q1[16];
#pragma unroll
    for (int d = 0; d < 16; d++) {
        q0[d] = __shfl_sync(0xffffffffu, qv, d);
        q1[d] = __shfl_sync(0xffffffffu, qv, 16 + d);
    }
    __syncthreads();
    for (int j = tid; j < 1280; j += 128) {
        int bi_i = j >> 5, off = (j & 31) * 4;
        int bi = s_idx[bi_i];
        size_t base = (size_t)(b * NR_ + bi) * 128 + off;
        *(float4*)&s_k[bi_i * 140 + off] = *(const float4*)&g_kbt[base];
        *(float4*)&s_v[bi_i * 132 + off] = *(const float4*)&g_vbt[base];
    }
    __syncthreads();
#pragma unroll
    for (int slot = 0; slot < 3; slot++) {
        int kk = lane + slot * 32;
        if (kk < 80) {
            int jb = kk >> 1, sp = kk & 1;
            const float4* kp = (const float4*)&s_k[jb * 140 + h * 32 + sp * 16];
            float4 k0 = kp[0], k1 = kp[1], k2 = kp[2], k3 = kp[3];
            float kd[16] = {k0.x,k0.y,k0.z,k0.w, k1.x,k1.y,k1.z,k1.w,
                            k2.x,k2.y,k2.z,k2.w, k3.x,k3.y,k3.z,k3.w};
            float l0 = 0.f, l1 = 0.f;
#pragma unroll
            for (int d = 0; d < 16; d++) { l0 += kd[d] * q0[d]; l1 += kd[d] * q1[d]; }
            s_l[h * 160 + kk]      = l0 * 0.125f;
            s_l[h * 160 + 80 + kk] = l1 * 0.125f;
        }
    }
    __syncwarp();
#pragma unroll
    for (int s = 0; s < 2; s++) {
        float vals[3];
        float m = -1e30f;
        int cnt = 0;
        for (int kk = lane; kk < 80; kk += 32) { vals[cnt] = s_l[h * 160 + s * 80 + kk]; m = fmaxf(m, vals[cnt]); cnt++; }
#pragma unroll
        for (int o = 16; o; o >>= 1) m = fmaxf(m, __shfl_xor_sync(0xffffffffu, m, o));
        float sum = 0.f;
        cnt = 0;
        for (int kk = lane; kk < 80; kk += 32) { float e = expf(vals[cnt] - m); vals[cnt] = e; sum += e; cnt++; }
#pragma unroll
        for (int o = 16; o; o >>= 1) sum += __shfl_xor_sync(0xffffffffu, sum, o);
        float inv = 1.f / sum;
        cnt = 0;
        for (int kk = lane; kk < 80; kk += 32) { s_l[h * 160 + s * 80 + kk] = vals[cnt] * inv; cnt++; }
    }
    __syncwarp();
    {
        int s = lane >> 4, d = lane & 15;
        float acc = 0.f;
#pragma unroll 8
        for (int kk = 0; kk < 80; kk++)
            acc += s_l[h * 160 + s * 80 + kk] * s_v[(kk >> 1) * 132 + h * 32 + (kk & 1) * 16 + d];
        g_obt[((size_t)(b * NR_ + r) * 4 + h) * 32 + lane] = acc;
    }
}

// ---------------- K9+K10 merged: fuse_o + fc1 (FFMA2), per-batch half ----------------
__global__ void __launch_bounds__(256) fuse_ofc1_kernel(const float* __restrict__ x,
                                                        const float* __restrict__ lw,
                                                        const float* __restrict__ lb,
                                                        const float* __restrict__ ow,
                                                        const float* __restrict__ ob,
                                                        const float* __restrict__ n2g,
                                                        const float* __restrict__ n2b,
                                                        const float* __restrict__ fc1w,
                                                        const float* __restrict__ bg,
                                                        const float* __restrict__ bb,
                                                        int b0) {
    int blk = blockIdx.x;
    int b = b0 + (blk >> 5);
    int tt0 = (blk & 31) << 6;
    __shared__ float s_tmp[64 * 68];
    __shared__ float s_w[64 * 64];
    int tid = threadIdx.x;
    for (int i = tid; i < 4096; i += 256) {
        int c = i >> 6, tl = i & 63;
        int t = tt0 + tl;
        const float* vp = g_v + (b * C_ + c) * T_;
        float vm1 = (t > 0) ? vp[t - 1] : 0.f;
        float v0 = vp[t];
        float vp1 = (t < T_ - 1) ? vp[t + 1] : 0.f;
        float lep = lw[c * 3 + 0] * vm1 + lw[c * 3 + 1] * v0 + lw[c * 3 + 2] * vp1 + lb[c];
        int hh = c >> 4, dd = c & 15, rr = t >> 1, sp = t & 1;
        float ov = g_obt[((size_t)(b * NR_ + rr) * 4 + hh) * 32 + sp * 16 + dd];
        s_tmp[c * 68 + tl] = ov + lep;
    }
    for (int i = tid; i < 4096; i += 256) {
        int ci = i >> 6, oc = i & 63;
        s_w[ci * 64 + oc] = ow[oc * 64 + ci];
    }
    __syncthreads();
    int tl = tid & 63;
    int og = tid >> 6;
    double acc2[8];
#pragma unroll
    for (int j = 0; j < 8; j++) acc2[j] = 0.0;
    for (int ci = 0; ci < 64; ci++) {
        float xv = s_tmp[ci * 68 + tl];
        double xp = pk2(xv, xv);
        const double* wp = (const double*)&s_w[ci * 64 + og * 16];
#pragma unroll
        for (int q = 0; q < 8; q++) ffma2(acc2[q], xp, wp[q]);
    }
    float acc[16];
#pragma unroll
    for (int q = 0; q < 8; q++) upk2(acc2[q], acc[2 * q], acc[2 * q + 1]);
    int t = tt0 + tl;
    float xn[16];
#pragma unroll
    for (int j = 0; j < 16; j++) {
        int oc = og * 16 + j;
        size_t o = (size_t)(b * C_ + oc) * T_ + t;
        float v = acc[j] + ob[oc] + x[o];
        g_x2[o] = v;
        xn[j] = v * bnsc(n2g[oc]) + n2b[oc];
    }
    __syncthreads();
#pragma unroll
    for (int j = 0; j < 16; j++) s_tmp[(og * 16 + j) * 68 + tl] = xn[j];
    for (int half = 0; half < 2; half++) {
        int oc2base = half * 64;
        __syncthreads();
        for (int i = tid; i < 4096; i += 256) {
            int oc2l = i & 63, ci = i >> 6;
            s_w[ci * 64 + oc2l] = fc1w[(oc2base + oc2l) * 64 + ci];
        }
        __syncthreads();
        double a2[8];
#pragma unroll
        for (int j = 0; j < 8; j++) a2[j] = 0.0;
        for (int ci = 0; ci < 64; ci++) {
            float xv = s_tmp[ci * 68 + tl];
            double xp = pk2(xv, xv);
            const double* wp = (const double*)&s_w[ci * 64 + og * 16];
#pragma unroll
            for (int q = 0; q < 8; q++) ffma2(a2[q], xp, wp[q]);
        }
        float av[16];
#pragma unroll
        for (int q = 0; q < 8; q++) upk2(a2[q], av[2 * q], av[2 * q + 1]);
#pragma unroll
        for (int j = 0; j < 16; j++) {
            int oc2 = oc2base + og * 16 + j;
            float r = av[j] * bnsc(bg[oc2]) + bb[oc2];
            g_h1[(size_t)(b * C2_ + oc2) * T_ + t] = fmaxf(r, 0.f);
        }
    }
}

// ---------------- K11: paired radix-4 FFT, per-batch half ----------------
__device__ __forceinline__ float2 cmulf(float2 a, float2 b) {
    return make_float2(a.x * b.x - a.y * b.y, a.x * b.y + a.y * b.x);
}

__device__ __forceinline__ void fft_stages(float2* sa, int tid, float neg) {
#pragma unroll
    for (int s = 0; s < 10; s += 2) {
        int L = 1 << s;
#pragma unroll
        for (int gi = 0; gi < 2; gi++) {
            int g = tid + gi * 256;
            int pos = g & (L - 1);
            int base = ((g >> s) << (s + 2)) + pos;
            float2 t1v = g_tw[pos << (10 - s)];
            float2 t2v = g_tw[pos << (9 - s)];
            float2 w1  = make_float2(t1v.x, neg * t1v.y);
            float2 w2a = make_float2(t2v.x, neg * t2v.y);
            float2 w2b = make_float2(t2v.y, -neg * t2v.x);
            float2 a = sa[base], b = sa[base + L], c = sa[base + 2 * L], d = sa[base + 3 * L];
            float2 wb = cmulf(w1, b), wd = cmulf(w1, d);
            float2 ap = make_float2(a.x + wb.x, a.y + wb.y);
            float2 bp = make_float2(a.x - wb.x, a.y - wb.y);
            float2 cp = make_float2(c.x + wd.x, c.y + wd.y);
            float2 dp = make_float2(c.x - wd.x, c.y - wd.y);
            float2 q1 = cmulf(w2a, cp), q2 = cmulf(w2b, dp);
            sa[base]         = make_float2(ap.x + q1.x, ap.y + q1.y);
            sa[base + 2 * L] = make_float2(ap.x - q1.x, ap.y - q1.y);
            sa[base + L]     = make_float2(bp.x + q2.x, bp.y + q2.y);
            sa[base + 3 * L] = make_float2(bp.x - q2.x, bp.y - q2.y);
        }
        __syncthreads();
    }
#pragma unroll
    for (int q = 0; q < 4; q++) {
        int j = tid + q * 256;
        float2 tv = g_tw[j];
        float2 w = make_float2(tv.x, neg * tv.y);
        float2 u = sa[j];
        float2 t2 = cmulf(w, sa[j + 1024]);
        sa[j]        = make_float2(u.x + t2.x, u.y + t2.y);
        sa[j + 1024] = make_float2(u.x - t2.x, u.y - t2.y);
    }
    __syncthreads();
}

__global__ void __launch_bounds__(256) fft_kernel(const float* __restrict__ fr,
                                                  const float* __restrict__ fi,
                                                  const float* __restrict__ frb,
                                                  const float* __restrict__ fib,
                                                  int b0) {
    int blk = blockIdx.x;
    int b = b0 + (blk >> 6), j = blk & 63;
    int c0 = 2 * j, c1 = 2 * j + 1;
    __shared__ float2 sa[2048];
    const float* in0 = g_h1 + (size_t)(b * C2_ + c0) * T_;
    const float* in1 = g_h1 + (size_t)(b * C2_ + c1) * T_;
    int tid = threadIdx.x;
    for (int t = tid; t < 2048; t += 256) {
        int p = __brev((unsigned)t) >> 21;
        sa[p] = make_float2(in0[t], in1[t]);
    }
    __syncthreads();
    fft_stages(sa, tid, 1.0f);

    float fr0 = fr[c0 * 128 + c0], fi0 = fi[c0 * 128 + c0];
    float rb0 = frb[c0], ib0 = fib[c0];
    float fr1 = fr[c1 * 128 + c1], fi1 = fi[c1 * 128 + c1];
    float rb1 = frb[c1], ib1 = fib[c1];
    const float sc = 0.022097086912079612f;
    float2 mixv[8];
#pragma unroll
    for (int q = 0; q < 8; q++) {
        int k = tid + q * 256;
        int m = (2048 - k) & 2047;
        float2 Zk = sa[k], Zm = sa[m];
        float Ar = 0.5f * sc * (Zk.x + Zm.x);
        float Ai = 0.5f * sc * (Zk.y - Zm.y);
        float Br = 0.5f * sc * (Zk.y + Zm.y);
        float Bi = 0.5f * sc * (Zm.x - Zk.x);
        float yk_r = fmaxf(Ar * fr0 - Ai * fi0 + rb0, 0.f);
        float yk_i = fmaxf(Ai * fr0 + Ar * fi0 + ib0, 0.f);
        float ym_r = fmaxf(Ar * fr0 + Ai * fi0 + rb0, 0.f);
        float ym_i = fmaxf(-Ai * fr0 + Ar * fi0 + ib0, 0.f);
        float Har = 0.5f * (yk_r + ym_r);
        float Hai = 0.5f * (yk_i - ym_i);
        float zk_r = fmaxf(Br * fr1 - Bi * fi1 + rb1, 0.f);
        float zk_i = fmaxf(Bi * fr1 + Br * fi1 + ib1, 0.f);
        float zm_r = fmaxf(Br * fr1 + Bi * fi1 + rb1, 0.f);
        float zm_i = fmaxf(-Bi * fr1 + Br * fi1 + ib1, 0.f);
        float Hbr = 0.5f * (zk_r + zm_r);
        float Hbi = 0.5f * (zk_i - zm_i);
        mixv[q] = make_float2(Har - Hbi, Hai + Hbr);
    }
    __syncthreads();
#pragma unroll
    for (int q = 0; q < 8; q++) {
        int k = tid + q * 256;
        sa[__brev((unsigned)k) >> 21] = mixv[q];
    }
    __syncthreads();
    fft_stages(sa, tid, -1.0f);

    float* out0 = g_h2 + (size_t)(b * C2_ + c0) * T_;
    float* out1 = g_h2 + (size_t)(b * C2_ + c1) * T_;
    for (int t = tid; t < 2048; t += 256) {
        float2 wv = sa[t];
        out0[t] = wv.x * sc;
        out1[t] = wv.y * sc;
    }
}

// ---------------- K12: fc2 (FFMA2), per-batch half ----------------
__global__ void __launch_bounds__(256) fc2_kernel(const float* __restrict__ w,
                                                  const float* __restrict__ bg,
                                                  const float* __restrict__ bb,
                                                  float* __restrict__ out,
                                                  int b0) {
    int blk = blockIdx.x;
    int b = b0 + (blk >> 6);
    int tt0 = (blk & 63) << 5;
    __shared__ float s_in[128 * 32];
    __shared__ float s_w[128 * 64];
    for (int i = threadIdx.x; i < 4096; i += 256) {
        int ci = i >> 5, tl = i & 31;
        s_in[ci * 32 + tl] = g_h2[(size_t)(b * C2_ + ci) * T_ + tt0 + tl];
    }
    for (int i = threadIdx.x; i < 8192; i += 256) {
        int oc = i & 63, ci = i >> 6;
        s_w[ci * 64 + oc] = w[oc * 128 + ci];
    }
    __syncthreads();
    int tl = threadIdx.x & 31;
    int og = threadIdx.x >> 5;
    double acc2[4];
#pragma unroll
    for (int j = 0; j < 4; j++) acc2[j] = 0.0;
    for (int ci = 0; ci < 128; ci++) {
        float xv = s_in[ci * 32 + tl];
        double xp = pk2(xv, xv);
        const double* wp = (const double*)&s_w[ci * 64 + og * 8];
#pragma unroll
        for (int q = 0; q < 4; q++) ffma2(acc2[q], xp, wp[q]);
    }
    float acc[8];
#pragma unroll
    for (int q = 0; q < 4; q++) upk2(acc2[q], acc[2 * q], acc[2 * q + 1]);
    int t = tt0 + tl;
#pragma unroll
    for (int j = 0; j < 8; j++) {
        int oc = og * 8 + j;
        size_t o = (size_t)(b * C_ + oc) * T_ + t;
        out[o] = acc[j] * bnsc(bg[oc]) + bb[oc] + g_x2[o];
    }
}

// ---------------- launch (three-stream pipelining) ----------------
static cudaStream_t g_s2 = nullptr, g_s3 = nullptr;
static cudaEvent_t g_ev_fork = nullptr, g_ev_q = nullptr, g_ev_k = nullptr,
                   g_ev_v = nullptr, g_ev_s1 = nullptr, g_ev_attn = nullptr,
                   g_ev_s2 = nullptr;

extern "C" void kernel_launch(void* const* d_in, const int* in_sizes, int n_in,
                              void* d_out, int out_size) {
    const float* x      = (const float*)d_in[0];
    const float* n1_g   = (const float*)d_in[1];
    const float* n1_b   = (const float*)d_in[2];
    const float* wq     = (const float*)d_in[3];
    const float* bnq_g  = (const float*)d_in[4];
    const float* bnq_b  = (const float*)d_in[5];
    const float* wk     = (const float*)d_in[6];
    const float* bnk_g  = (const float*)d_in[7];
    const float* bnk_b  = (const float*)d_in[8];
    const float* wv     = (const float*)d_in[9];
    const float* lepe_w = (const float*)d_in[10];
    const float* lepe_b = (const float*)d_in[11];
    const float* out_w  = (const float*)d_in[12];
    const float* out_b  = (const float*)d_in[13];
    const float* n2_g   = (const float*)d_in[14];
    const float* n2_b   = (const float*)d_in[15];
    const float* fc1_w  = (const float*)d_in[16];
    const float* bn1_g  = (const float*)d_in[17];
    const float* bn1_b  = (const float*)d_in[18];
    const float* fr     = (const float*)d_in[19];
    const float* fi     = (const float*)d_in[20];
    const float* frb    = (const float*)d_in[21];
    const float* fib    = (const float*)d_in[22];
    const float* fc2_w  = (const float*)d_in[23];
    const float* bn2_g  = (const float*)d_in[24];
    const float* bn2_b  = (const float*)d_in[25];
    float* out = (float*)d_out;

    if (!g_s2) {
        cudaStreamCreateWithFlags(&g_s2, cudaStreamNonBlocking);
        cudaStreamCreateWithFlags(&g_s3, cudaStreamNonBlocking);
        cudaEventCreateWithFlags(&g_ev_fork, cudaEventDisableTiming);
        cudaEventCreateWithFlags(&g_ev_q, cudaEventDisableTiming);
        cudaEventCreateWithFlags(&g_ev_k, cudaEventDisableTiming);
        cudaEventCreateWithFlags(&g_ev_v, cudaEventDisableTiming);
        cudaEventCreateWithFlags(&g_ev_s1, cudaEventDisableTiming);
        cudaEventCreateWithFlags(&g_ev_attn, cudaEventDisableTiming);
        cudaEventCreateWithFlags(&g_ev_s2, cudaEventDisableTiming);
    }

    prep_kernel<<<1, 256>>>(n1_g, n1_b, wq, bnq_g, bnq_b, wk, bnk_g, bnk_b, wv);
    cudaEventRecord(g_ev_fork, 0);
    cudaStreamWaitEvent(g_s2, g_ev_fork, 0);
    cudaStreamWaitEvent(g_s3, g_ev_fork, 0);

    // s3: twiddle + conv1v (independent)
    twiddle_kernel<<<4, 256, 0, g_s3>>>();
    conv1v_kernel<<<512, 256, 0, g_s3>>>(x);
    cudaEventRecord(g_ev_v, g_s3);

    // s2: k-half conv3; main: q-half conv3 (concurrent)
    conv3qk_kernel<<<512, 128, 0, g_s2>>>(x, 512);
    cudaEventRecord(g_ev_k, g_s2);
    conv3qk_kernel<<<512, 128>>>(x, 0);
    cudaEventRecord(g_ev_q, 0);

    // gemm+topk halves: main needs k-half, s2 needs q-half
    cudaStreamWaitEvent(g_s2, g_ev_q, 0);
    gemm_ar_kernel<<<512, 256, 0, g_s2>>>(8);
    topk_kernel<<<8 * NR_, 256, 0, g_s2>>>(8);
    cudaEventRecord(g_ev_s1, g_s2);

    cudaStreamWaitEvent(0, g_ev_k, 0);
    gemm_ar_kernel<<<512, 256>>>(0);
    topk_kernel<<<8 * NR_, 256>>>(0);

    // attention needs both topk halves + conv1v (g_vbt)
    cudaStreamWaitEvent(0, g_ev_s1, 0);
    cudaStreamWaitEvent(0, g_ev_v, 0);
    attn_kernel<<<B_ * NR_, 128>>>();
    cudaEventRecord(g_ev_attn, 0);
    cudaStreamWaitEvent(g_s2, g_ev_attn, 0);

    // phase-2: per-batch-half chains on both streams
    fuse_ofc1_kernel<<<256, 256, 0, g_s2>>>(x, lepe_w, lepe_b, out_w, out_b,
                                            n2_g, n2_b, fc1_w, bn1_g, bn1_b, 8);
    fft_kernel<<<512, 256, 0, g_s2>>>(fr, fi, frb, fib, 8);
    fc2_kernel<<<512, 256, 0, g_s2>>>(fc2_w, bn2_g, bn2_b, out, 8);
    cudaEventRecord(g_ev_s2, g_s2);

    fuse_ofc1_kernel<<<256, 256>>>(x, lepe_w, lepe_b, out_w, out_b,
                                   n2_g, n2_b, fc1_w, bn1_g, bn1_b, 0);
    fft_kernel<<<512, 256>>>(fr, fi, frb, fib, 0);
    fc2_kernel<<<512, 256>>>(fc2_w, bn2_g, bn2_b, out, 0);
    cudaStreamWaitEvent(0, g_ev_s2, 0);

    (void)in_sizes; (void)n_in; (void)out_size;
}

// round 12
// speedup vs baseline: 1.1281x; 1.1281x over previous
#include <cuda_runtime.h>
#include <cuda_fp16.h>
#include <math.h>

#define B_ 16
#define C_ 64
#define T_ 2048
#define H_ 4
#define HD_ 16
#define NR_ 1024
#define TOPK_ 40
#define C2_ 128

// ---------------- packed fp32x2 helpers (sm_103a FFMA2) ----------------
__device__ __forceinline__ double pk2(float lo, float hi) {
    double r; asm("mov.b64 %0, {%1,%2};" : "=d"(r) : "f"(lo), "f"(hi)); return r;
}
__device__ __forceinline__ void upk2(double v, float& lo, float& hi) {
    asm("mov.b64 {%0,%1}, %2;" : "=f"(lo), "=f"(hi) : "d"(v));
}
__device__ __forceinline__ void ffma2(double& acc, double a, double b) {
    asm("fma.rn.f32x2 %0, %1, %2, %0;" : "+d"(acc) : "d"(a), "d"(b));
}

// ---------------- scratch (device globals; no allocation) ----------------
__device__ float g_fwq[3*C_*C_];
__device__ float g_fwk[3*C_*C_];
__device__ float g_fwv[C_*C_];
__device__ float g_bq3[3*C_];
__device__ float g_bk3[3*C_];
__device__ float g_bv [C_];
__device__ float g_v  [B_*C_*T_];
__device__ float g_qr [B_*C_*NR_];
__device__ float g_kr [B_*C_*NR_];
__device__ float g_ar [B_*NR_*NR_];
__device__ int   g_idx[B_*NR_*TOPK_];
__device__ float g_qbt[B_*NR_*128];
__device__ __half g_kbth[B_*NR_*128];
__device__ __half g_vbth[B_*NR_*128];
__device__ float g_obt[B_*NR_*128];
__device__ float g_x2 [B_*C_*T_];
__device__ float g_h1 [B_*C2_*T_];
__device__ float g_h2 [B_*C2_*T_];
__device__ float2 g_tw[1024];

__device__ __forceinline__ float bnsc(float g) { return g * rsqrtf(1.0f + 1e-5f); }

// ---------------- K0: twiddle ----------------
__global__ void twiddle_kernel() {
    int k = blockIdx.x * blockDim.x + threadIdx.x;
    if (k < 1024) {
        double a = -2.0 * 3.14159265358979323846 * (double)k / 2048.0;
        g_tw[k] = make_float2((float)cos(a), (float)sin(a));
    }
}

// ---------------- K1: fold BN into conv weights ----------------
__global__ void __launch_bounds__(256) prep_kernel(const float* __restrict__ n1_g,
                                                   const float* __restrict__ n1_b,
                                                   const float* __restrict__ wq,
                                                   const float* __restrict__ bnq_g,
                                                   const float* __restrict__ bnq_b,
                                                   const float* __restrict__ wk,
                                                   const float* __restrict__ bnk_g,
                                                   const float* __restrict__ bnk_b,
                                                   const float* __restrict__ wv) {
    int tid = threadIdx.x;
    for (int i = tid; i < 3 * C_ * C_; i += 256) {
        int oc = i & 63;
        int ci = (i >> 6) & 63;
        int h  = i >> 12;
        float s1 = bnsc(n1_g[ci]);
        g_fwq[i] = wq[(oc * 64 + ci) * 3 + h] * s1 * bnsc(bnq_g[oc]);
        g_fwk[i] = wk[(oc * 64 + ci) * 3 + h] * s1 * bnsc(bnk_g[oc]);
    }
    for (int i = tid; i < C_ * C_; i += 256) {
        int oc = i & 63, ci = i >> 6;
        g_fwv[i] = wv[oc * 64 + ci] * bnsc(n1_g[ci]);
    }
    if (tid < 64) {
        int oc = tid;
        float Sq[3] = {0.f, 0.f, 0.f}, Sk[3] = {0.f, 0.f, 0.f}, Sv = 0.f;
        for (int ci = 0; ci < 64; ci++) {
            float b1 = n1_b[ci];
#pragma unroll
            for (int h = 0; h < 3; h++) {
                Sq[h] += wq[(oc * 64 + ci) * 3 + h] * b1;
                Sk[h] += wk[(oc * 64 + ci) * 3 + h] * b1;
            }
            Sv += wv[oc * 64 + ci] * b1;
        }
        float sq = bnsc(bnq_g[oc]), sk = bnsc(bnk_g[oc]);
        float mq = sq * (Sq[0] + Sq[1] + Sq[2]) + bnq_b[oc];
        float mk = sk * (Sk[0] + Sk[1] + Sk[2]) + bnk_b[oc];
        g_bq3[oc]       = mq - sq * Sq[0];
        g_bq3[64 + oc]  = mq;
        g_bq3[128 + oc] = mq - sq * Sq[2];
        g_bk3[oc]       = mk - sk * Sk[0];
        g_bk3[64 + oc]  = mk;
        g_bk3[128 + oc] = mk - sk * Sk[2];
        g_bv[oc] = Sv;
    }
}

// ---------------- K2: conv k=3 + BN folded (FFMA2); k-branch emits fp16 bt ----------------
__global__ void __launch_bounds__(128) conv3qk_kernel(const float* __restrict__ x, int blk0) {
    int blk = blk0 + blockIdx.x;
    int oh = blk & 1;
    int tt0 = ((blk >> 1) & 15) * 128;
    int b  = (blk >> 5) & 15;
    int which = blk >> 9;

    const float* w   = which ? g_fwk : g_fwq;
    const float* b3  = which ? g_bk3 : g_bq3;
    float* pr        = which ? g_kr  : g_qr;

    __shared__ float s_in[32 * 132];
    __shared__ float s_w[3 * 32 * 32];

    int tid = threadIdx.x;
    int tl4 = (tid & 31) * 4;
    int og  = tid >> 5;

    double acc2[4][4];
#pragma unroll
    for (int t = 0; t < 4; t++)
#pragma unroll
        for (int j = 0; j < 4; j++) acc2[t][j] = 0.0;

    for (int chunk = 0; chunk < 2; chunk++) {
        int ci0 = chunk * 32;
        for (int i = tid; i < 32 * 132; i += 128) {
            int ci = i / 132, jj = i % 132;
            int gt = tt0 + jj - 1;
            s_in[i] = (gt >= 0 && gt < T_ && jj < 130) ? x[(b * C_ + ci0 + ci) * T_ + gt] : 0.f;
        }
        for (int i = tid; i < 3072; i += 128) {
            int ocl = i & 31;
            int cil = (i >> 5) & 31;
            int h = i >> 10;
            s_w[i] = w[(h * 64 + ci0 + cil) * 64 + oh * 32 + ocl];
        }
        __syncthreads();
        for (int cil = 0; cil < 32; cil++) {
            float xs[6];
            float4 xa = *(const float4*)&s_in[cil * 132 + tl4];
            xs[0] = xa.x; xs[1] = xa.y; xs[2] = xa.z; xs[3] = xa.w;
            xs[4] = s_in[cil * 132 + tl4 + 4];
            xs[5] = s_in[cil * 132 + tl4 + 5];
            double px[6];
#pragma unroll
            for (int i = 0; i < 6; i++) px[i] = pk2(xs[i], xs[i]);
#pragma unroll
            for (int h = 0; h < 3; h++) {
                const double* wp = (const double*)&s_w[(h * 32 + cil) * 32 + og * 8];
                double w01 = wp[0], w23 = wp[1], w45 = wp[2], w67 = wp[3];
#pragma unroll
                for (int t = 0; t < 4; t++) {
                    ffma2(acc2[t][0], px[t + h], w01);
                    ffma2(acc2[t][1], px[t + h], w23);
                    ffma2(acc2[t][2], px[t + h], w45);
                    ffma2(acc2[t][3], px[t + h], w67);
                }
            }
        }
        __syncthreads();
    }
    float f[4][8];
#pragma unroll
    for (int t = 0; t < 4; t++)
#pragma unroll
        for (int j = 0; j < 4; j++) upk2(acc2[t][j], f[t][2 * j], f[t][2 * j + 1]);
#pragma unroll
    for (int j = 0; j < 8; j++) {
        int oc = oh * 32 + og * 8 + j;
        float bm = b3[64 + oc];
#pragma unroll
        for (int t = 0; t < 4; t++) {
            int gt = tt0 + tl4 + t;
            float bias = (gt == 0) ? b3[oc] : ((gt == T_ - 1) ? b3[128 + oc] : bm);
            f[t][j] += bias;
        }
        int r0 = (tt0 + tl4) >> 1;
        float2 p2 = make_float2(0.5f * (f[0][j] + f[1][j]), 0.5f * (f[2][j] + f[3][j]));
        *(float2*)&pr[(b * C_ + oc) * NR_ + r0] = p2;
    }
    {
        int h = oh * 2 + (og >> 1);
        int d0 = (og & 1) * 8;
        if (which == 0) {
#pragma unroll
            for (int t = 0; t < 4; t++) {
                int gt = tt0 + tl4 + t;
                int r = gt >> 1, s = gt & 1;
                float* dst = &g_qbt[((size_t)(b * NR_ + r) * 4 + h) * 32 + s * 16 + d0];
                *(float4*)dst       = make_float4(f[t][0], f[t][1], f[t][2], f[t][3]);
                *(float4*)(dst + 4) = make_float4(f[t][4], f[t][5], f[t][6], f[t][7]);
            }
        } else {
#pragma unroll
            for (int t = 0; t < 4; t++) {
                int gt = tt0 + tl4 + t;
                int r = gt >> 1, s = gt & 1;
                __half2 hh[4];
                hh[0] = __floats2half2_rn(f[t][0], f[t][1]);
                hh[1] = __floats2half2_rn(f[t][2], f[t][3]);
                hh[2] = __floats2half2_rn(f[t][4], f[t][5]);
                hh[3] = __floats2half2_rn(f[t][6], f[t][7]);
                *(uint4*)&g_kbth[((size_t)(b * NR_ + r) * 4 + h) * 32 + s * 16 + d0] = *(uint4*)hh;
            }
        }
    }
}

// ---------------- K3: conv k=1 (v) (FFMA2); emits v fp32 + vbt fp16 ----------------
__global__ void __launch_bounds__(256) conv1v_kernel(const float* __restrict__ x) {
    int blk = blockIdx.x;
    int b = blk >> 5;
    int tt0 = (blk & 31) * 64;
    __shared__ float s_in[64 * 68];
    __shared__ float s_w[64 * 64];
    int tid = threadIdx.x;
    int tq = tid & 15;
    int ocg = tid >> 4;

    for (int i = tid; i < 4096; i += 256) {
        int ci = i >> 6, tl = i & 63;
        s_in[ci * 68 + tl] = x[(b * C_ + ci) * T_ + tt0 + tl];
    }
    for (int i = tid; i < 4096; i += 256) {
        int ci = i >> 6, oc = i & 63;
        s_w[ci * 64 + oc] = g_fwv[ci * 64 + oc];
    }
    __syncthreads();

    double acc2[4][2];
#pragma unroll
    for (int t = 0; t < 4; t++) { acc2[t][0] = 0.0; acc2[t][1] = 0.0; }
    for (int ci = 0; ci < 64; ci++) {
        float4 xa = *(const float4*)&s_in[ci * 68 + tq * 4];
        const double* wp = (const double*)&s_w[ci * 64 + ocg * 4];
        double w01 = wp[0], w23 = wp[1];
        double px[4] = {pk2(xa.x, xa.x), pk2(xa.y, xa.y), pk2(xa.z, xa.z), pk2(xa.w, xa.w)};
#pragma unroll
        for (int t = 0; t < 4; t++) {
            ffma2(acc2[t][0], px[t], w01);
            ffma2(acc2[t][1], px[t], w23);
        }
    }
    float f[4][4];
#pragma unroll
    for (int t = 0; t < 4; t++) {
        upk2(acc2[t][0], f[t][0], f[t][1]);
        upk2(acc2[t][1], f[t][2], f[t][3]);
    }
    int oc0 = ocg * 4;
    {
        float4 bv4 = *(const float4*)&g_bv[oc0];
        float bvr[4] = {bv4.x, bv4.y, bv4.z, bv4.w};
#pragma unroll
        for (int j = 0; j < 4; j++)
#pragma unroll
            for (int t = 0; t < 4; t++) f[t][j] += bvr[j];
    }
#pragma unroll
    for (int j = 0; j < 4; j++) {
        int oc = oc0 + j;
        *(float4*)&g_v[(b * C_ + oc) * T_ + tt0 + tq * 4] =
            make_float4(f[0][j], f[1][j], f[2][j], f[3][j]);
    }
    {
        int h = ocg >> 2;
        int d0 = (ocg & 3) * 4;
#pragma unroll
        for (int t = 0; t < 4; t++) {
            int gt = tt0 + tq * 4 + t;
            int r = gt >> 1, s = gt & 1;
            __half2 hh[2];
            hh[0] = __floats2half2_rn(f[t][0], f[t][1]);
            hh[1] = __floats2half2_rn(f[t][2], f[t][3]);
            *(uint2*)&g_vbth[((size_t)(b * NR_ + r) * 4 + h) * 32 + s * 16 + d0] = *(uint2*)hh;
        }
    }
}

// ---------------- K5: a_r (TF32 3x), per-batch half ----------------
__device__ __forceinline__ unsigned f2tf32(float x) {
    unsigned r;
    asm("cvt.rna.tf32.f32 %0, %1;" : "=r"(r) : "f"(x));
    return r;
}
__device__ __forceinline__ void mma_tf32(float* d, unsigned a0, unsigned a1, unsigned a2, unsigned a3,
                                         unsigned b0, unsigned b1) {
    asm("mma.sync.aligned.m16n8k8.row.col.f32.tf32.tf32.f32 "
        "{%0,%1,%2,%3}, {%4,%5,%6,%7}, {%8,%9}, {%0,%1,%2,%3};"
        : "+f"(d[0]), "+f"(d[1]), "+f"(d[2]), "+f"(d[3])
        : "r"(a0), "r"(a1), "r"(a2), "r"(a3), "r"(b0), "r"(b1));
}

__global__ void __launch_bounds__(256) gemm_ar_kernel(int b0) {
    int blk = blockIdx.x;
    int b = b0 + (blk >> 6);
    int mt = (blk >> 3) & 7;
    int nt = blk & 7;
    int m0 = mt * 128, n0 = nt * 128;
    __shared__ float As[128 * 33];
    __shared__ float Bs[128 * 33];
    const float* qp = g_qr + b * C_ * NR_;
    const float* kp = g_kr + b * C_ * NR_;
    int tid = threadIdx.x;
    int warp = tid >> 5, lane = tid & 31;
    int wm = warp >> 2, wn = warp & 3;
    int m0w = wm * 64, n0w = wn * 32;
    int qr = lane >> 2, qc = lane & 3;

    float d[4][4][4];
#pragma unroll
    for (int i = 0; i < 4; i++)
#pragma unroll
        for (int j = 0; j < 4; j++)
#pragma unroll
            for (int q = 0; q < 4; q++) d[i][j][q] = 0.f;

    for (int k0 = 0; k0 < 64; k0 += 32) {
        for (int i = tid; i < 4096; i += 256) {
            int c = i >> 7, m = i & 127;
            As[m * 33 + c] = qp[(k0 + c) * NR_ + m0 + m];
            Bs[m * 33 + c] = kp[(k0 + c) * NR_ + n0 + m];
        }
        __syncthreads();
#pragma unroll
        for (int ks = 0; ks < 32; ks += 8) {
            unsigned ahi[4][4], alo[4][4];
#pragma unroll
            for (int mf = 0; mf < 4; mf++) {
                int rb = (m0w + mf * 16 + qr) * 33 + ks + qc;
                float a[4] = {As[rb], As[rb + 8 * 33], As[rb + 4], As[rb + 8 * 33 + 4]};
#pragma unroll
                for (int q = 0; q < 4; q++) {
                    unsigned h = f2tf32(a[q]);
                    ahi[mf][q] = h;
                    alo[mf][q] = f2tf32(a[q] - __uint_as_float(h));
                }
            }
            unsigned bhi[4][2], blo[4][2];
#pragma unroll
            for (int nf = 0; nf < 4; nf++) {
                int cb = (n0w + nf * 8 + qr) * 33 + ks + qc;
                float bv[2] = {Bs[cb], Bs[cb + 4]};
#pragma unroll
                for (int q = 0; q < 2; q++) {
                    unsigned h = f2tf32(bv[q]);
                    bhi[nf][q] = h;
                    blo[nf][q] = f2tf32(bv[q] - __uint_as_float(h));
                }
            }
#pragma unroll
            for (int mf = 0; mf < 4; mf++)
#pragma unroll
                for (int nf = 0; nf < 4; nf++) {
                    mma_tf32(d[mf][nf], alo[mf][0], alo[mf][1], alo[mf][2], alo[mf][3],
                             bhi[nf][0], bhi[nf][1]);
                    mma_tf32(d[mf][nf], ahi[mf][0], ahi[mf][1], ahi[mf][2], ahi[mf][3],
                             blo[nf][0], blo[nf][1]);
                    mma_tf32(d[mf][nf], ahi[mf][0], ahi[mf][1], ahi[mf][2], ahi[mf][3],
                             bhi[nf][0], bhi[nf][1]);
                }
        }
        __syncthreads();
    }
#pragma unroll
    for (int mf = 0; mf < 4; mf++) {
        int mrow = m0 + m0w + mf * 16 + qr;
#pragma unroll
        for (int nf = 0; nf < 4; nf++) {
            int ncol = n0 + n0w + nf * 8 + 2 * qc;
            *(float2*)&g_ar[(size_t)(b * NR_ + mrow) * NR_ + ncol] =
                make_float2(d[mf][nf][0], d[mf][nf][1]);
            *(float2*)&g_ar[(size_t)(b * NR_ + mrow + 8) * NR_ + ncol] =
                make_float2(d[mf][nf][2], d[mf][nf][3]);
        }
    }
}

// ---------------- K6: top-40, per-batch half ----------------
__global__ void __launch_bounds__(256) topk_kernel(int b0) {
    int row = b0 * NR_ + blockIdx.x;
    int tid = threadIdx.x;
    int lane = tid & 31, wid = tid >> 5;
    unsigned lmlt = (1u << lane) - 1u;
    const float4* ap = (const float4*)(g_ar + (size_t)row * NR_);
    __shared__ int whist[8][256];
    __shared__ int htot[256];
    __shared__ unsigned long long cA[1024];
    __shared__ unsigned long long cB[1024];
    __shared__ int s_thr, s_need, s_outc, s_nsrc, s_nb;

    unsigned long long kv[4];
    {
        float4 v4 = ap[tid];
        float vv[4] = {v4.x, v4.y, v4.z, v4.w};
#pragma unroll
        for (int j = 0; j < 4; j++) {
            unsigned u = __float_as_uint(vv[j]);
            u = (u & 0x80000000u) ? ~u : (u | 0x80000000u);
            kv[j] = ((unsigned long long)u << 32) | (unsigned)(tid * 4 + j);
        }
    }
    if (tid == 0) { s_outc = 0; s_need = TOPK_; }
    int* outp = g_idx + row * TOPK_;

    for (int level = 0; level < 4; level++) {
        unsigned long long* src = (level & 1) ? cA : cB;
        unsigned long long* dst = (level & 1) ? cB : cA;
        int shift = 56 - level * 8;
        if (level == 0) {
            for (int i = tid; i < 2048; i += 256) ((int*)whist)[i] = 0;
            if (tid == 0) s_nb = 0;
            __syncthreads();
#pragma unroll
            for (int j = 0; j < 4; j++)
                atomicAdd(&whist[wid][(int)((kv[j] >> shift) & 255)], 1);
            __syncthreads();
            int sum = 0;
#pragma unroll
            for (int w = 0; w < 8; w++) sum += whist[w][tid];
            htot[tid] = sum;
        } else {
            htot[tid] = 0;
            if (tid == 0) s_nb = 0;
            __syncthreads();
            int nsrc = s_nsrc;
            for (int i = tid; i < nsrc; i += 256)
                atomicAdd(&htot[(int)((src[i] >> shift) & 255)], 1);
        }
        __syncthreads();
        if (tid < 32) {
            int base = 255 - lane * 8;
            int part[8]; int tot = 0;
#pragma unroll
            for (int q = 0; q < 8; q++) { part[q] = htot[base - q]; tot += part[q]; }
            int pre = tot;
#pragma unroll
            for (int o = 1; o < 32; o <<= 1) {
                int v = __shfl_up_sync(0xffffffffu, pre, o);
                if (lane >= o) pre += v;
            }
            pre -= tot;
            int need = s_need;
            int cum = pre;
#pragma unroll
            for (int q = 0; q < 8; q++) {
                int c = part[q];
                if (cum < need && cum + c >= need) s_thr = base - q;
                cum += c;
            }
        }
        __syncthreads();
        int thr = s_thr;
        int nsrc = (level == 0) ? 1024 : s_nsrc;
        int niter = (level == 0) ? 4 : ((nsrc + 255) >> 8);
        for (int it = 0; it < niter; it++) {
            unsigned long long v = 0ull;
            bool valid;
            if (level == 0) { v = kv[it]; valid = true; }
            else { int i = it * 256 + tid; valid = (i < nsrc); if (valid) v = src[i]; }
            int by = valid ? (int)((v >> shift) & 255) : -1;
            bool gt = (by > thr), eq = (by == thr);
            unsigned mg = __ballot_sync(0xffffffffu, gt);
            if (mg) {
                int ldr = __ffs(mg) - 1;
                int bp = 0;
                if (lane == ldr) bp = atomicAdd(&s_outc, __popc(mg));
                bp = __shfl_sync(0xffffffffu, bp, ldr);
                if (gt) outp[bp + __popc(mg & lmlt)] = (int)(v & 0xffffffffu);
            }
            unsigned me = __ballot_sync(0xffffffffu, eq);
            if (me) {
                int ldr = __ffs(me) - 1;
                int bp = 0;
                if (lane == ldr) bp = atomicAdd(&s_nb, __popc(me));
                bp = __shfl_sync(0xffffffffu, bp, ldr);
                if (eq) dst[bp + __popc(me & lmlt)] = v;
            }
        }
        __syncthreads();
        if (tid == 0) { s_need = TOPK_ - s_outc; s_nsrc = s_nb; }
        __syncthreads();
        if (s_nsrc == s_need || level == 3) {
            int base = TOPK_ - s_need;
            for (int i = tid; i < s_need; i += 256)
                outp[base + i] = (int)(dst[i] & 0xffffffffu);
            break;
        }
    }
}

// ---------------- K8: attention, fp16 K/V gather ----------------
__global__ void __launch_bounds__(128) attn_kernel() {
    int blk = blockIdx.x;
    int b = blk >> 10, r = blk & (NR_ - 1);
    int tid = threadIdx.x;
    int lane = tid & 31, h = tid >> 5;
    __shared__ __half s_k[40 * 136];
    __shared__ __half s_v[40 * 136];
    __shared__ float s_l[4 * 160];
    __shared__ int s_idx[40];

    if (tid < 40) s_idx[tid] = g_idx[(b * NR_ + r) * TOPK_ + tid];
    float qv = g_qbt[((size_t)(b * NR_ + r) * 4 + h) * 32 + lane];
    float q0[16], q1[16];
#pragma unroll
    for (int d = 0; d < 16; d++) {
        q0[d] = __shfl_sync(0xffffffffu, qv, d);
        q1[d] = __shfl_sync(0xffffffffu, qv, 16 + d);
    }
    __syncthreads();
    // stage K and V (fp16): 40 blocks x 128 halves = 640 uint4 each
    for (int j = tid; j < 640; j += 128) {
        int bi_i = j >> 4, off = (j & 15) * 8;
        int bi = s_idx[bi_i];
        size_t base = (size_t)(b * NR_ + bi) * 128 + off;
        *(uint4*)&s_k[bi_i * 136 + off] = *(const uint4*)&g_kbth[base];
        *(uint4*)&s_v[bi_i * 136 + off] = *(const uint4*)&g_vbth[base];
    }
    __syncthreads();
#pragma unroll
    for (int slot = 0; slot < 3; slot++) {
        int kk = lane + slot * 32;
        if (kk < 80) {
            int jb = kk >> 1, sp = kk & 1;
            const uint4* kp = (const uint4*)&s_k[jb * 136 + h * 32 + sp * 16];
            uint4 ka = kp[0], kb = kp[1];
            const __half2* ha = (const __half2*)&ka;
            const __half2* hb = (const __half2*)&kb;
            float kd[16];
#pragma unroll
            for (int q = 0; q < 4; q++) {
                float2 fa = __half22float2(ha[q]);
                float2 fb = __half22float2(hb[q]);
                kd[2 * q]     = fa.x; kd[2 * q + 1] = fa.y;
                kd[8 + 2 * q] = fb.x; kd[8 + 2 * q + 1] = fb.y;
            }
            float l0 = 0.f, l1 = 0.f;
#pragma unroll
            for (int d = 0; d < 16; d++) { l0 += kd[d] * q0[d]; l1 += kd[d] * q1[d]; }
            s_l[h * 160 + kk]      = l0 * 0.125f;
            s_l[h * 160 + 80 + kk] = l1 * 0.125f;
        }
    }
    __syncwarp();
#pragma unroll
    for (int s = 0; s < 2; s++) {
        float vals[3];
        float m = -1e30f;
        int cnt = 0;
        for (int kk = lane; kk < 80; kk += 32) { vals[cnt] = s_l[h * 160 + s * 80 + kk]; m = fmaxf(m, vals[cnt]); cnt++; }
#pragma unroll
        for (int o = 16; o; o >>= 1) m = fmaxf(m, __shfl_xor_sync(0xffffffffu, m, o));
        float sum = 0.f;
        cnt = 0;
        for (int kk = lane; kk < 80; kk += 32) { float e = expf(vals[cnt] - m); vals[cnt] = e; sum += e; cnt++; }
#pragma unroll
        for (int o = 16; o; o >>= 1) sum += __shfl_xor_sync(0xffffffffu, sum, o);
        float inv = 1.f / sum;
        cnt = 0;
        for (int kk = lane; kk < 80; kk += 32) { s_l[h * 160 + s * 80 + kk] = vals[cnt] * inv; cnt++; }
    }
    __syncwarp();
    {
        int s = lane >> 4, d = lane & 15;
        float acc = 0.f;
#pragma unroll 8
        for (int kk = 0; kk < 80; kk++)
            acc += s_l[h * 160 + s * 80 + kk] *
                   __half2float(s_v[(kk >> 1) * 136 + h * 32 + (kk & 1) * 16 + d]);
        g_obt[((size_t)(b * NR_ + r) * 4 + h) * 32 + lane] = acc;
    }
}

// ---------------- K9+K10 merged: fuse_o + fc1 (FFMA2), per-batch half ----------------
__global__ void __launch_bounds__(256) fuse_ofc1_kernel(const float* __restrict__ x,
                                                        const float* __restrict__ lw,
                                                        const float* __restrict__ lb,
                                                        const float* __restrict__ ow,
                                                        const float* __restrict__ ob,
                                                        const float* __restrict__ n2g,
                                                        const float* __restrict__ n2b,
                                                        const float* __restrict__ fc1w,
                                                        const float* __restrict__ bg,
                                                        const float* __restrict__ bb,
                                                        int b0) {
    int blk = blockIdx.x;
    int b = b0 + (blk >> 5);
    int tt0 = (blk & 31) << 6;
    __shared__ float s_tmp[64 * 68];
    __shared__ float s_w[64 * 64];
    int tid = threadIdx.x;
    for (int i = tid; i < 4096; i += 256) {
        int c = i >> 6, tl = i & 63;
        int t = tt0 + tl;
        const float* vp = g_v + (b * C_ + c) * T_;
        float vm1 = (t > 0) ? vp[t - 1] : 0.f;
        float v0 = vp[t];
        float vp1 = (t < T_ - 1) ? vp[t + 1] : 0.f;
        float lep = lw[c * 3 + 0] * vm1 + lw[c * 3 + 1] * v0 + lw[c * 3 + 2] * vp1 + lb[c];
        int hh = c >> 4, dd = c & 15, rr = t >> 1, sp = t & 1;
        float ov = g_obt[((size_t)(b * NR_ + rr) * 4 + hh) * 32 + sp * 16 + dd];
        s_tmp[c * 68 + tl] = ov + lep;
    }
    for (int i = tid; i < 4096; i += 256) {
        int ci = i >> 6, oc = i & 63;
        s_w[ci * 64 + oc] = ow[oc * 64 + ci];
    }
    __syncthreads();
    int tl = tid & 63;
    int og = tid >> 6;
    double acc2[8];
#pragma unroll
    for (int j = 0; j < 8; j++) acc2[j] = 0.0;
    for (int ci = 0; ci < 64; ci++) {
        float xv = s_tmp[ci * 68 + tl];
        double xp = pk2(xv, xv);
        const double* wp = (const double*)&s_w[ci * 64 + og * 16];
#pragma unroll
        for (int q = 0; q < 8; q++) ffma2(acc2[q], xp, wp[q]);
    }
    float acc[16];
#pragma unroll
    for (int q = 0; q < 8; q++) upk2(acc2[q], acc[2 * q], acc[2 * q + 1]);
    int t = tt0 + tl;
    float xn[16];
#pragma unroll
    for (int j = 0; j < 16; j++) {
        int oc = og * 16 + j;
        size_t o = (size_t)(b * C_ + oc) * T_ + t;
        float v = acc[j] + ob[oc] + x[o];
        g_x2[o] = v;
        xn[j] = v * bnsc(n2g[oc]) + n2b[oc];
    }
    __syncthreads();
#pragma unroll
    for (int j = 0; j < 16; j++) s_tmp[(og * 16 + j) * 68 + tl] = xn[j];
    for (int half = 0; half < 2; half++) {
        int oc2base = half * 64;
        __syncthreads();
        for (int i = tid; i < 4096; i += 256) {
            int oc2l = i & 63, ci = i >> 6;
            s_w[ci * 64 + oc2l] = fc1w[(oc2base + oc2l) * 64 + ci];
        }
        __syncthreads();
        double a2[8];
#pragma unroll
        for (int j = 0; j < 8; j++) a2[j] = 0.0;
        for (int ci = 0; ci < 64; ci++) {
            float xv = s_tmp[ci * 68 + tl];
            double xp = pk2(xv, xv);
            const double* wp = (const double*)&s_w[ci * 64 + og * 16];
#pragma unroll
            for (int q = 0; q < 8; q++) ffma2(a2[q], xp, wp[q]);
        }
        float av[16];
#pragma unroll
        for (int q = 0; q < 8; q++) upk2(a2[q], av[2 * q], av[2 * q + 1]);
#pragma unroll
        for (int j = 0; j < 16; j++) {
            int oc2 = oc2base + og * 16 + j;
            float r = av[j] * bnsc(bg[oc2]) + bb[oc2];
            g_h1[(size_t)(b * C2_ + oc2) * T_ + t] = fmaxf(r, 0.f);
        }
    }
}

// ---------------- K11: paired radix-4 FFT, per-batch half ----------------
__device__ __forceinline__ float2 cmulf(float2 a, float2 b) {
    return make_float2(a.x * b.x - a.y * b.y, a.x * b.y + a.y * b.x);
}

__device__ __forceinline__ void fft_stages(float2* sa, int tid, float neg) {
#pragma unroll
    for (int s = 0; s < 10; s += 2) {
        int L = 1 << s;
#pragma unroll
        for (int gi = 0; gi < 2; gi++) {
            int g = tid + gi * 256;
            int pos = g & (L - 1);
            int base = ((g >> s) << (s + 2)) + pos;
            float2 t1v = g_tw[pos << (10 - s)];
            float2 t2v = g_tw[pos << (9 - s)];
            float2 w1  = make_float2(t1v.x, neg * t1v.y);
            float2 w2a = make_float2(t2v.x, neg * t2v.y);
            float2 w2b = make_float2(t2v.y, -neg * t2v.x);
            float2 a = sa[base], b = sa[base + L], c = sa[base + 2 * L], d = sa[base + 3 * L];
            float2 wb = cmulf(w1, b), wd = cmulf(w1, d);
            float2 ap = make_float2(a.x + wb.x, a.y + wb.y);
            float2 bp = make_float2(a.x - wb.x, a.y - wb.y);
            float2 cp = make_float2(c.x + wd.x, c.y + wd.y);
            float2 dp = make_float2(c.x - wd.x, c.y - wd.y);
            float2 q1 = cmulf(w2a, cp), q2 = cmulf(w2b, dp);
            sa[base]         = make_float2(ap.x + q1.x, ap.y + q1.y);
            sa[base + 2 * L] = make_float2(ap.x - q1.x, ap.y - q1.y);
            sa[base + L]     = make_float2(bp.x + q2.x, bp.y + q2.y);
            sa[base + 3 * L] = make_float2(bp.x - q2.x, bp.y - q2.y);
        }
        __syncthreads();
    }
#pragma unroll
    for (int q = 0; q < 4; q++) {
        int j = tid + q * 256;
        float2 tv = g_tw[j];
        float2 w = make_float2(tv.x, neg * tv.y);
        float2 u = sa[j];
        float2 t2 = cmulf(w, sa[j + 1024]);
        sa[j]        = make_float2(u.x + t2.x, u.y + t2.y);
        sa[j + 1024] = make_float2(u.x - t2.x, u.y - t2.y);
    }
    __syncthreads();
}

__global__ void __launch_bounds__(256) fft_kernel(const float* __restrict__ fr,
                                                  const float* __restrict__ fi,
                                                  const float* __restrict__ frb,
                                                  const float* __restrict__ fib,
                                                  int b0) {
    int blk = blockIdx.x;
    int b = b0 + (blk >> 6), j = blk & 63;
    int c0 = 2 * j, c1 = 2 * j + 1;
    __shared__ float2 sa[2048];
    const float* in0 = g_h1 + (size_t)(b * C2_ + c0) * T_;
    const float* in1 = g_h1 + (size_t)(b * C2_ + c1) * T_;
    int tid = threadIdx.x;
    for (int t = tid; t < 2048; t += 256) {
        int p = __brev((unsigned)t) >> 21;
        sa[p] = make_float2(in0[t], in1[t]);
    }
    __syncthreads();
    fft_stages(sa, tid, 1.0f);

    float fr0 = fr[c0 * 128 + c0], fi0 = fi[c0 * 128 + c0];
    float rb0 = frb[c0], ib0 = fib[c0];
    float fr1 = fr[c1 * 128 + c1], fi1 = fi[c1 * 128 + c1];
    float rb1 = frb[c1], ib1 = fib[c1];
    const float sc = 0.022097086912079612f;
    float2 mixv[8];
#pragma unroll
    for (int q = 0; q < 8; q++) {
        int k = tid + q * 256;
        int m = (2048 - k) & 2047;
        float2 Zk = sa[k], Zm = sa[m];
        float Ar = 0.5f * sc * (Zk.x + Zm.x);
        float Ai = 0.5f * sc * (Zk.y - Zm.y);
        float Br = 0.5f * sc * (Zk.y + Zm.y);
        float Bi = 0.5f * sc * (Zm.x - Zk.x);
        float yk_r = fmaxf(Ar * fr0 - Ai * fi0 + rb0, 0.f);
        float yk_i = fmaxf(Ai * fr0 + Ar * fi0 + ib0, 0.f);
        float ym_r = fmaxf(Ar * fr0 + Ai * fi0 + rb0, 0.f);
        float ym_i = fmaxf(-Ai * fr0 + Ar * fi0 + ib0, 0.f);
        float Har = 0.5f * (yk_r + ym_r);
        float Hai = 0.5f * (yk_i - ym_i);
        float zk_r = fmaxf(Br * fr1 - Bi * fi1 + rb1, 0.f);
        float zk_i = fmaxf(Bi * fr1 + Br * fi1 + ib1, 0.f);
        float zm_r = fmaxf(Br * fr1 + Bi * fi1 + rb1, 0.f);
        float zm_i = fmaxf(-Bi * fr1 + Br * fi1 + ib1, 0.f);
        float Hbr = 0.5f * (zk_r + zm_r);
        float Hbi = 0.5f * (zk_i - zm_i);
        mixv[q] = make_float2(Har - Hbi, Hai + Hbr);
    }
    __syncthreads();
#pragma unroll
    for (int q = 0; q < 8; q++) {
        int k = tid + q * 256;
        sa[__brev((unsigned)k) >> 21] = mixv[q];
    }
    __syncthreads();
    fft_stages(sa, tid, -1.0f);

    float* out0 = g_h2 + (size_t)(b * C2_ + c0) * T_;
    float* out1 = g_h2 + (size_t)(b * C2_ + c1) * T_;
    for (int t = tid; t < 2048; t += 256) {
        float2 wv = sa[t];
        out0[t] = wv.x * sc;
        out1[t] = wv.y * sc;
    }
}

// ---------------- K12: fc2 (FFMA2), per-batch half ----------------
__global__ void __launch_bounds__(256) fc2_kernel(const float* __restrict__ w,
                                                  const float* __restrict__ bg,
                                                  const float* __restrict__ bb,
                                                  float* __restrict__ out,
                                                  int b0) {
    int blk = blockIdx.x;
    int b = b0 + (blk >> 6);
    int tt0 = (blk & 63) << 5;
    __shared__ float s_in[128 * 32];
    __shared__ float s_w[128 * 64];
    for (int i = threadIdx.x; i < 4096; i += 256) {
        int ci = i >> 5, tl = i & 31;
        s_in[ci * 32 + tl] = g_h2[(size_t)(b * C2_ + ci) * T_ + tt0 + tl];
    }
    for (int i = threadIdx.x; i < 8192; i += 256) {
        int oc = i & 63, ci = i >> 6;
        s_w[ci * 64 + oc] = w[oc * 128 + ci];
    }
    __syncthreads();
    int tl = threadIdx.x & 31;
    int og = threadIdx.x >> 5;
    double acc2[4];
#pragma unroll
    for (int j = 0; j < 4; j++) acc2[j] = 0.0;
    for (int ci = 0; ci < 128; ci++) {
        float xv = s_in[ci * 32 + tl];
        double xp = pk2(xv, xv);
        const double* wp = (const double*)&s_w[ci * 64 + og * 8];
#pragma unroll
        for (int q = 0; q < 4; q++) ffma2(acc2[q], xp, wp[q]);
    }
    float acc[8];
#pragma unroll
    for (int q = 0; q < 4; q++) upk2(acc2[q], acc[2 * q], acc[2 * q + 1]);
    int t = tt0 + tl;
#pragma unroll
    for (int j = 0; j < 8; j++) {
        int oc = og * 8 + j;
        size_t o = (size_t)(b * C_ + oc) * T_ + t;
        out[o] = acc[j] * bnsc(bg[oc]) + bb[oc] + g_x2[o];
    }
}

// ---------------- launch (three-stream pipelining) ----------------
static cudaStream_t g_s2 = nullptr, g_s3 = nullptr;
static cudaEvent_t g_ev_fork = nullptr, g_ev_q = nullptr, g_ev_k = nullptr,
                   g_ev_v = nullptr, g_ev_s1 = nullptr, g_ev_attn = nullptr,
                   g_ev_s2 = nullptr;

extern "C" void kernel_launch(void* const* d_in, const int* in_sizes, int n_in,
                              void* d_out, int out_size) {
    const float* x      = (const float*)d_in[0];
    const float* n1_g   = (const float*)d_in[1];
    const float* n1_b   = (const float*)d_in[2];
    const float* wq     = (const float*)d_in[3];
    const float* bnq_g  = (const float*)d_in[4];
    const float* bnq_b  = (const float*)d_in[5];
    const float* wk     = (const float*)d_in[6];
    const float* bnk_g  = (const float*)d_in[7];
    const float* bnk_b  = (const float*)d_in[8];
    const float* wv     = (const float*)d_in[9];
    const float* lepe_w = (const float*)d_in[10];
    const float* lepe_b = (const float*)d_in[11];
    const float* out_w  = (const float*)d_in[12];
    const float* out_b  = (const float*)d_in[13];
    const float* n2_g   = (const float*)d_in[14];
    const float* n2_b   = (const float*)d_in[15];
    const float* fc1_w  = (const float*)d_in[16];
    const float* bn1_g  = (const float*)d_in[17];
    const float* bn1_b  = (const float*)d_in[18];
    const float* fr     = (const float*)d_in[19];
    const float* fi     = (const float*)d_in[20];
    const float* frb    = (const float*)d_in[21];
    const float* fib    = (const float*)d_in[22];
    const float* fc2_w  = (const float*)d_in[23];
    const float* bn2_g  = (const float*)d_in[24];
    const float* bn2_b  = (const float*)d_in[25];
    float* out = (float*)d_out;

    if (!g_s2) {
        cudaStreamCreateWithFlags(&g_s2, cudaStreamNonBlocking);
        cudaStreamCreateWithFlags(&g_s3, cudaStreamNonBlocking);
        cudaEventCreateWithFlags(&g_ev_fork, cudaEventDisableTiming);
        cudaEventCreateWithFlags(&g_ev_q, cudaEventDisableTiming);
        cudaEventCreateWithFlags(&g_ev_k, cudaEventDisableTiming);
        cudaEventCreateWithFlags(&g_ev_v, cudaEventDisableTiming);
        cudaEventCreateWithFlags(&g_ev_s1, cudaEventDisableTiming);
        cudaEventCreateWithFlags(&g_ev_attn, cudaEventDisableTiming);
        cudaEventCreateWithFlags(&g_ev_s2, cudaEventDisableTiming);
    }

    prep_kernel<<<1, 256>>>(n1_g, n1_b, wq, bnq_g, bnq_b, wk, bnk_g, bnk_b, wv);
    cudaEventRecord(g_ev_fork, 0);
    cudaStreamWaitEvent(g_s2, g_ev_fork, 0);
    cudaStreamWaitEvent(g_s3, g_ev_fork, 0);

    // s3: twiddle + conv1v (independent)
    twiddle_kernel<<<4, 256, 0, g_s3>>>();
    conv1v_kernel<<<512, 256, 0, g_s3>>>(x);
    cudaEventRecord(g_ev_v, g_s3);

    // s2: k-half conv3; main: q-half conv3 (concurrent)
    conv3qk_kernel<<<512, 128, 0, g_s2>>>(x, 512);
    cudaEventRecord(g_ev_k, g_s2);
    conv3qk_kernel<<<512, 128>>>(x, 0);
    cudaEventRecord(g_ev_q, 0);

    // gemm+topk halves: main needs k-half, s2 needs q-half
    cudaStreamWaitEvent(g_s2, g_ev_q, 0);
    gemm_ar_kernel<<<512, 256, 0, g_s2>>>(8);
    topk_kernel<<<8 * NR_, 256, 0, g_s2>>>(8);
    cudaEventRecord(g_ev_s1, g_s2);

    cudaStreamWaitEvent(0, g_ev_k, 0);
    gemm_ar_kernel<<<512, 256>>>(0);
    topk_kernel<<<8 * NR_, 256>>>(0);

    // attention needs both topk halves + conv1v (g_vbth)
    cudaStreamWaitEvent(0, g_ev_s1, 0);
    cudaStreamWaitEvent(0, g_ev_v, 0);
    attn_kernel<<<B_ * NR_, 128>>>();
    cudaEventRecord(g_ev_attn, 0);
    cudaStreamWaitEvent(g_s2, g_ev_attn, 0);

    // phase-2: per-batch-half chains on both streams
    fuse_ofc1_kernel<<<256, 256, 0, g_s2>>>(x, lepe_w, lepe_b, out_w, out_b,
                                            n2_g, n2_b, fc1_w, bn1_g, bn1_b, 8);
    fft_kernel<<<512, 256, 0, g_s2>>>(fr, fi, frb, fib, 8);
    fc2_kernel<<<512, 256, 0, g_s2>>>(fc2_w, bn2_g, bn2_b, out, 8);
    cudaEventRecord(g_ev_s2, g_s2);

    fuse_ofc1_kernel<<<256, 256>>>(x, lepe_w, lepe_b, out_w, out_b,
                                   n2_g, n2_b, fc1_w, bn1_g, bn1_b, 0);
    fft_kernel<<<512, 256>>>(fr, fi, frb, fib, 0);
    fc2_kernel<<<512, 256>>>(fc2_w, bn2_g, bn2_b, out, 0);
    cudaStreamWaitEvent(0, g_ev_s2, 0);

    (void)in_sizes; (void)n_in; (void)out_size;
}